// round 12
// baseline (speedup 1.0000x reference)
#include <cuda_runtime.h>
#include <math.h>

#define Bc   2
#define Nc   9600
#define BNc  19200
#define Kc   10
#define DWc  150
#define PI_F 3.14159265358979323846f
#define NCH  75     // vlad N-chunks
#define CHN  128    // nodes per vlad chunk
#define YCH  64     // y-projection chunks
#define DEPTH 20    // knn push-buffer depth per thread (shared by its 2 queries)

// ---------------- scratch (device-symbol access ONLY from device code) ----------------
__device__ float4 d_pts4[BNc];
__device__ int    d_edges[BNc * Kc];
__device__ float  d_h1[BNc * 128], d_res1[BNc * 128], d_g1[BNc * 128];
__device__ float  d_es[BNc], d_ed[BNc];
__device__ float  d_h2[BNc * 256], d_res2[BNc * 256], d_g2[BNc * 256];
__device__ float  d_act[BNc * 64];
__device__ float  d_vpart[Bc * NCH * 256 * 64];
__device__ float  d_vlad[Bc * 256 * 64];
__device__ float  d_colsq[Bc * 64];
__device__ float  d_ypart[Bc * YCH * 256];

// exact strict-< sorted insert (keeps earlier candidate on ties: FIFO order)
__device__ __forceinline__ void chain_insert(float (&bd)[Kc], int (&bi)[Kc],
                                             float dv, int iv) {
    bd[Kc - 1] = dv; bi[Kc - 1] = iv;
#pragma unroll
    for (int s = Kc - 1; s > 0; --s) {
        if (bd[s] < bd[s - 1]) {
            float td = bd[s]; bd[s] = bd[s - 1]; bd[s - 1] = td;
            int   ti = bi[s]; bi[s] = bi[s - 1]; bi[s - 1] = ti;
        }
    }
}

// ---------------- 1+3a. fused: spherical->cartesian + GAT1 (3->128) ------------------
__global__ void ptsgat1_kernel(const float* __restrict__ depth,
                               const float* __restrict__ W,
                               const float* __restrict__ as_,
                               const float* __restrict__ ad_,
                               const float* __restrict__ RW)
{
    int gw   = (blockIdx.x * blockDim.x + threadIdx.x) >> 5;
    int lane = threadIdx.x & 31;
    if (gw >= BNc) return;

    // point (uniform across warp; redundant per-lane compute is cheap)
    int n = gw % Nc;
    int i = n / DWc;
    int j = n % DWc;
    float theta = -PI_F + (float)j * (2.0f * PI_F / 149.0f);
    float phi   = -0.5f * PI_F + (float)i * (PI_F / 63.0f);
    float r = depth[gw];
    float cp = cosf(phi), sp = sinf(phi);
    float st = sinf(theta), ct = cosf(theta);
    float px = r * cp * st;
    float py = r * sp;
    float pz = r * cp * ct;
    if (lane == 0)
        d_pts4[gw] = make_float4(px, py, pz, px * px + py * py + pz * pz);

    float e1 = 0.f, e2 = 0.f;
#pragma unroll
    for (int u = 0; u < 4; u++) {
        int c = lane + u * 32;
        float hv = px * W[c] + py * W[128 + c] + pz * W[256 + c];
        d_h1[gw * 128 + c]   = hv;
        d_res1[gw * 128 + c] = px * RW[c] + py * RW[128 + c] + pz * RW[256 + c];
        e1 += hv * as_[c];
        e2 += hv * ad_[c];
    }
#pragma unroll
    for (int o = 16; o > 0; o >>= 1) {
        e1 += __shfl_down_sync(0xffffffffu, e1, o);
        e2 += __shfl_down_sync(0xffffffffu, e2, o);
    }
    if (lane == 0) { d_es[gw] = e1; d_ed[gw] = e2; }
}

// ---------------- 2. kNN: 8-way split, 2 queries/thread, push buffer, drains ---------
// grid = 600, block = 128. 32 queries/block; thread = (query-pair qp_, partition h).
// Queries q0 = qb*32+qp_, q1 = q0+16. Score s = |c|^2 - 2 q.c via premultiplied query.
__global__ __launch_bounds__(128) void knn_kernel() {
    int b  = blockIdx.x / 300;
    int qb = blockIdx.x % 300;
    int t  = threadIdx.x;      // 0..127
    int h  = t & 7;            // candidate partition (c mod 8)
    int qp_ = t >> 3;          // 0..15
    int q0 = qb * 32 + qp_;
    int q1 = q0 + 16;
    int base = b * Nc;

    __shared__ float4 stile[640];                 // 10240 B
    __shared__ float2 sbuf[DEPTH * 128];          // 20480 B (overlaid by merge arrays)
    float* sval = (float*)sbuf;                   // 32*8*10 floats = 10240 B
    int*   sidx = (int*)((char*)sbuf + 10240);    // 10240 B

    float4 P0 = d_pts4[base + q0];
    float4 P1 = d_pts4[base + q1];
    float q0x = -2.f * P0.x, q0y = -2.f * P0.y, q0z = -2.f * P0.z;
    float q1x = -2.f * P1.x, q1y = -2.f * P1.y, q1z = -2.f * P1.z;

    // ---- window thresholds (values-only, branchless min/max network) ----
    float th0, th1;
    {
        float wd[Kc];
#pragma unroll
        for (int k = 0; k < Kc; k++) wd[k] = 3.4e38f;
        int wlo = q0 - 64; if (wlo < 0) wlo = 0; if (wlo > Nc - 128) wlo = Nc - 128;
        wlo &= ~7;
#pragma unroll 4
        for (int jj = 0; jj < 16; jj++) {
            float4 p = d_pts4[base + wlo + jj * 8 + h];
            float d2 = fmaf(q0x, p.x, fmaf(q0y, p.y, fmaf(q0z, p.z, p.w)));
#pragma unroll
            for (int s = Kc - 1; s > 0; --s) wd[s] = fminf(wd[s], fmaxf(wd[s - 1], d2));
            wd[0] = fminf(wd[0], d2);
        }
        th0 = wd[Kc - 1];
    }
    {
        float wd[Kc];
#pragma unroll
        for (int k = 0; k < Kc; k++) wd[k] = 3.4e38f;
        int wlo = q1 - 64; if (wlo < 0) wlo = 0; if (wlo > Nc - 128) wlo = Nc - 128;
        wlo &= ~7;
#pragma unroll 4
        for (int jj = 0; jj < 16; jj++) {
            float4 p = d_pts4[base + wlo + jj * 8 + h];
            float d2 = fmaf(q1x, p.x, fmaf(q1y, p.y, fmaf(q1z, p.z, p.w)));
#pragma unroll
            for (int s = Kc - 1; s > 0; --s) wd[s] = fminf(wd[s], fmaxf(wd[s - 1], d2));
            wd[0] = fminf(wd[0], d2);
        }
        th1 = wd[Kc - 1];
    }

    float bd0[Kc], bd1[Kc]; int bi0[Kc], bi1[Kc];
#pragma unroll
    for (int k = 0; k < Kc; k++) {
        bd0[k] = 3.4e38f; bi0[k] = -1;
        bd1[k] = 3.4e38f; bi1[k] = -1;
    }
    int cnt = 0;

#define DRAIN2()                                                           \
    do {                                                                   \
        for (int j_ = 0; ; j_++) {                                         \
            if (!__ballot_sync(0xffffffffu, j_ < cnt)) break;              \
            if (j_ < cnt) {                                                \
                float2 e_ = sbuf[j_ * 128 + t];                            \
                int iv_ = __float_as_int(e_.y);                            \
                int ix_ = iv_ & 0xFFFF;                                    \
                if (iv_ < 0x10000) {                                       \
                    if (e_.x < bd0[Kc - 1]) chain_insert(bd0, bi0, e_.x, ix_); \
                } else {                                                   \
                    if (e_.x < bd1[Kc - 1]) chain_insert(bd1, bi1, e_.x, ix_); \
                }                                                          \
            }                                                              \
        }                                                                  \
        cnt = 0;                                                           \
        th0 = fminf(th0, bd0[Kc - 1]);                                     \
        th1 = fminf(th1, bd1[Kc - 1]);                                     \
    } while (0)

    // ---- main scan: 15 tiles x 640 points, groups of 8 candidates ----
    for (int tile = 0; tile < 15; tile++) {
        int t0 = tile * 640;
        for (int i = t; i < 640; i += 128)
            stile[i] = d_pts4[base + t0 + i];
        __syncthreads();

        for (int cc = 0; cc < 80; cc += 8) {
            float sv0[8], sv1[8];
#pragma unroll
            for (int u = 0; u < 8; u++) {
                float4 p = stile[(cc + u) * 8 + h];
                sv0[u] = fmaf(q0x, p.x, fmaf(q0y, p.y, fmaf(q0z, p.z, p.w)));
                sv1[u] = fmaf(q1x, p.x, fmaf(q1y, p.y, fmaf(q1z, p.z, p.w)));
            }
            float m0 = fminf(fminf(fminf(sv0[0], sv0[1]), fminf(sv0[2], sv0[3])),
                             fminf(fminf(sv0[4], sv0[5]), fminf(sv0[6], sv0[7])));
            float m1 = fminf(fminf(fminf(sv1[0], sv1[1]), fminf(sv1[2], sv1[3])),
                             fminf(fminf(sv1[4], sv1[5]), fminf(sv1[6], sv1[7])));

            // warp-uniform overflow drain: after it every lane has cnt<=4; group adds <=16
            if (__ballot_sync(0xffffffffu, cnt >= DEPTH - 16 + 1)) DRAIN2();

            if (m0 <= th0) {
#pragma unroll
                for (int u = 0; u < 8; u++) {
                    if (sv0[u] <= th0) {
                        sbuf[cnt * 128 + t] =
                            make_float2(sv0[u], __int_as_float(t0 + (cc + u) * 8 + h));
                        cnt++;
                    }
                }
            }
            if (m1 <= th1) {
#pragma unroll
                for (int u = 0; u < 8; u++) {
                    if (sv1[u] <= th1) {
                        sbuf[cnt * 128 + t] =
                            make_float2(sv1[u],
                                __int_as_float(0x10000 | (t0 + (cc + u) * 8 + h)));
                        cnt++;
                    }
                }
            }
        }
        __syncthreads();
    }

    DRAIN2();
    __syncthreads();   // everyone done with sbuf before merge arrays overlay it

    // store per-partition lists: q_local 0..31 = qp_ (+16 for q1)
    int lb0 = ((qp_)      * 8 + h) * Kc;
    int lb1 = ((qp_ + 16) * 8 + h) * Kc;
#pragma unroll
    for (int k = 0; k < Kc; k++) {
        sval[lb0 + k] = bd0[k]; sidx[lb0 + k] = bi0[k];
        sval[lb1 + k] = bd1[k]; sidx[lb1 + k] = bi1[k];
    }
    __syncthreads();

    // exact (value, index)-lexicographic 8-list merge; 32 threads, one query each
    if (h < 2) {
        int q_local = qp_ + 16 * h;
        int q = qb * 32 + q_local;
        int p[8] = {0, 0, 0, 0, 0, 0, 0, 0};
        int lbase = q_local * 8 * Kc;
#pragma unroll
        for (int outk = 0; outk < Kc; outk++) {
            float bv = 3.5e38f; int bix = 0x7fffffff; int bl = 0;
#pragma unroll
            for (int l = 0; l < 8; l++) {
                if (p[l] < Kc) {
                    float v = sval[lbase + l * Kc + p[l]];
                    int   ix = sidx[lbase + l * Kc + p[l]];
                    if (v < bv || (v == bv && ix < bix)) { bv = v; bix = ix; bl = l; }
                }
            }
            p[bl]++;
            d_edges[(base + q) * Kc + outk] = bix;
        }
    }
#undef DRAIN2
}

// ---------------- 3b. attention aggregate ----------------
template <int LAYER, int C, bool RELU>
__global__ void attn_kernel(const float* __restrict__ bias)
{
    const float* __restrict__ h   = (LAYER == 1) ? d_h1   : d_h2;
    const float* __restrict__ res = (LAYER == 1) ? d_res1 : d_res2;
    float* __restrict__ out       = (LAYER == 1) ? d_g1   : d_g2;

    int gw   = (blockIdx.x * blockDim.x + threadIdx.x) >> 5;
    int lane = threadIdx.x & 31;
    if (gw >= BNc) return;
    int b = gw / Nc;

    float edv = d_ed[gw];
    float lg[Kc];
    int   nb[Kc];
#pragma unroll
    for (int k = 0; k < Kc; k++) {
        nb[k] = b * Nc + d_edges[gw * Kc + k];
        float e = d_es[nb[k]] + edv;
        lg[k] = (e > 0.f) ? e : 0.2f * e;
    }
    float m = lg[0];
#pragma unroll
    for (int k = 1; k < Kc; k++) m = fmaxf(m, lg[k]);
    float sum = 0.f;
#pragma unroll
    for (int k = 0; k < Kc; k++) { lg[k] = expf(lg[k] - m); sum += lg[k]; }
    float inv = 1.0f / sum;

    for (int c = lane; c < C; c += 32) {
        float acc = 0.f;
#pragma unroll
        for (int k = 0; k < Kc; k++) acc += lg[k] * h[nb[k] * C + c];
        float v = acc * inv + bias[c] + res[gw * C + c];
        out[gw * C + c] = RELU ? fmaxf(v, 0.f) : v;
    }
}

// ---------------- 3c. GAT2 matmul (128->256), 16 nodes/block, fused e_src/e_dst -------
__global__ void mm2_kernel(const float* __restrict__ W,
                           const float* __restrict__ RW,
                           const float* __restrict__ as_,
                           const float* __restrict__ ad_)
{
    __shared__ float xs[16 * 128];
    __shared__ float wred[2][16][8];
    int nb0 = blockIdx.x * 16;
    int t = threadIdx.x;
    for (int i = t; i < 16 * 128; i += 256)
        xs[i] = d_g1[nb0 * 128 + i];
    __syncthreads();

    int c = t;
    float acc[16], ar[16];
#pragma unroll
    for (int r = 0; r < 16; r++) { acc[r] = 0.f; ar[r] = 0.f; }

    for (int i = 0; i < 128; i++) {
        float w  = W[i * 256 + c];
        float rw = RW[i * 256 + c];
#pragma unroll
        for (int r = 0; r < 16; r++) {
            float xv = xs[r * 128 + i];
            acc[r] += xv * w;
            ar[r]  += xv * rw;
        }
    }

    float asv = as_[c], adv = ad_[c];
    int lane = t & 31, wid = t >> 5;
#pragma unroll
    for (int r = 0; r < 16; r++) {
        d_h2[(nb0 + r) * 256 + c]   = acc[r];
        d_res2[(nb0 + r) * 256 + c] = ar[r];
        float v1 = acc[r] * asv;
        float v2 = acc[r] * adv;
#pragma unroll
        for (int o = 16; o > 0; o >>= 1) {
            v1 += __shfl_down_sync(0xffffffffu, v1, o);
            v2 += __shfl_down_sync(0xffffffffu, v2, o);
        }
        if (lane == 0) { wred[0][r][wid] = v1; wred[1][r][wid] = v2; }
    }
    __syncthreads();
    if (t < 32) {
        int r = t & 15, which = t >> 4;
        float s = 0.f;
#pragma unroll
        for (int w = 0; w < 8; w++) s += wred[which][r][w];
        if (which == 0) d_es[nb0 + r] = s;
        else            d_ed[nb0 + r] = s;
    }
}

// ---------------- 4a. NetVLAD cluster softmax ----------------
__global__ void act_kernel(const float* __restrict__ cw,
                           const float* __restrict__ cb)
{
    __shared__ float xs[8 * 256];
    __shared__ float red[64];
    int nb0 = blockIdx.x * 8;
    for (int i = threadIdx.x; i < 8 * 256; i += 64)
        xs[i] = d_g2[nb0 * 256 + i];
    __syncthreads();

    int k = threadIdx.x;
    float acc[8];
#pragma unroll
    for (int r = 0; r < 8; r++) acc[r] = cb[k];
    for (int dd = 0; dd < 256; dd++) {
        float w = cw[dd * 64 + k];
#pragma unroll
        for (int r = 0; r < 8; r++) acc[r] += xs[r * 256 + dd] * w;
    }

#pragma unroll
    for (int r = 0; r < 8; r++) {
        red[k] = acc[r];
        __syncthreads();
        for (int s = 32; s > 0; s >>= 1) {
            if (k < s) red[k] = fmaxf(red[k], red[k + s]);
            __syncthreads();
        }
        float m = red[0];
        __syncthreads();
        float e = expf(acc[r] - m);
        red[k] = e;
        __syncthreads();
        for (int s = 32; s > 0; s >>= 1) {
            if (k < s) red[k] += red[k + s];
            __syncthreads();
        }
        float sum = red[0];
        __syncthreads();
        d_act[(nb0 + r) * 64 + k] = e / sum;
    }
}

// ---------------- 4b. vlad partial ----------------
__global__ void vlad_partial() {
    int b  = blockIdx.x / NCH;
    int ch = blockIdx.x % NCH;
    int t  = threadIdx.x;
    int d  = t & 255;
    int kg = t >> 8;
    int base = b * Nc + ch * CHN;

    __shared__ float sact[16 * 64];
    float acc[16];
#pragma unroll
    for (int j = 0; j < 16; j++) acc[j] = 0.f;

    int nl = t >> 6, kk = t & 63;
    for (int n0 = 0; n0 < CHN; n0 += 16) {
        sact[t] = d_act[(base + n0 + nl) * 64 + kk];
        __syncthreads();
#pragma unroll
        for (int j = 0; j < 16; j++) {
            float g = d_g2[(base + n0 + j) * 256 + d];
            const float4* arow = (const float4*)&sact[j * 64 + kg * 16];
            float4 a0 = arow[0], a1 = arow[1], a2 = arow[2], a3 = arow[3];
            acc[0]  += g * a0.x; acc[1]  += g * a0.y; acc[2]  += g * a0.z; acc[3]  += g * a0.w;
            acc[4]  += g * a1.x; acc[5]  += g * a1.y; acc[6]  += g * a1.z; acc[7]  += g * a1.w;
            acc[8]  += g * a2.x; acc[9]  += g * a2.y; acc[10] += g * a2.z; acc[11] += g * a2.w;
            acc[12] += g * a3.x; acc[13] += g * a3.y; acc[14] += g * a3.z; acc[15] += g * a3.w;
        }
        __syncthreads();
    }

    float4* dst = (float4*)&d_vpart[(((b * NCH) + ch) * 256 + d) * 64 + kg * 16];
    dst[0] = make_float4(acc[0],  acc[1],  acc[2],  acc[3]);
    dst[1] = make_float4(acc[4],  acc[5],  acc[6],  acc[7]);
    dst[2] = make_float4(acc[8],  acc[9],  acc[10], acc[11]);
    dst[3] = make_float4(acc[12], acc[13], acc[14], acc[15]);
}

// ---------------- 4c. vlad finish ----------------
__global__ void vlad_finish(const float* __restrict__ cw2) {
    int b  = blockIdx.x >> 6;
    int k  = blockIdx.x & 63;
    int dd = threadIdx.x;

    float part = 0.f;
    for (int n = dd; n < Nc; n += 256)
        part += d_act[(b * Nc + n) * 64 + k];
    __shared__ float red[256];
    red[dd] = part;
    __syncthreads();
    for (int s = 128; s > 0; s >>= 1) {
        if (dd < s) red[dd] += red[dd + s];
        __syncthreads();
    }
    float asum = red[0];
    __syncthreads();

    float v = 0.f;
#pragma unroll 5
    for (int ch = 0; ch < NCH; ch++)
        v += d_vpart[((b * NCH + ch) * 256 + dd) * 64 + k];
    v -= asum * cw2[dd * 64 + k];

    red[dd] = v * v;
    __syncthreads();
    for (int s = 128; s > 0; s >>= 1) {
        if (dd < s) red[dd] += red[dd + s];
        __syncthreads();
    }
    float ss  = red[0];
    float den = fmaxf(sqrtf(ss), 1e-12f);
    d_vlad[(b * 256 + dd) * 64 + k] = v / den;
    if (dd == 0) d_colsq[b * 64 + k] = ss / (den * den);
}

// ---------------- 4d. y partial projection ----------------
__global__ void y_partial(const float* __restrict__ h1w) {
    int b  = blockIdx.x / YCH;
    int ch = blockIdx.x % YCH;
    int o  = threadIdx.x;
    __shared__ float sv[256];
    sv[o] = d_vlad[b * 16384 + ch * 256 + o];
    __syncthreads();
    float acc = 0.f;
#pragma unroll 4
    for (int j = 0; j < 256; j++)
        acc += sv[j] * h1w[(ch * 256 + j) * 256 + o];
    d_ypart[(b * YCH + ch) * 256 + o] = acc;
}

// ---------------- 4e. reduce y + gate + output ----------------
__global__ void out_kernel(const float* __restrict__ h1b,
                           const float* __restrict__ gw,
                           const float* __restrict__ gb,
                           float* __restrict__ out)
{
    int b = blockIdx.x;
    int o = threadIdx.x;
    __shared__ float sc[64];
    __shared__ float gs;
    if (o < 64) sc[o] = d_colsq[b * 64 + o];
    __syncthreads();
    if (o == 0) {
        float s = 0.f;
        for (int i = 0; i < 64; i++) s += sc[i];
        gs = 1.0f / fmaxf(sqrtf(s), 1e-12f);
    }
    __syncthreads();

    float acc = 0.f;
#pragma unroll
    for (int ch = 0; ch < YCH; ch++)
        acc += d_ypart[(b * YCH + ch) * 256 + o];
    float y = acc * gs + h1b[o];

    __shared__ float sy[256];
    sy[o] = y;
    __syncthreads();
    float g = gb[o];
    for (int j = 0; j < 256; j++) g += sy[j] * gw[j * 256 + o];
    out[b * 256 + o] = y * (1.0f / (1.0f + expf(-g)));
}

// ---------------- launch ----------------
extern "C" void kernel_launch(void* const* d_in, const int* in_sizes, int n_in,
                              void* d_out, int out_size) {
    const float* depth    = (const float*)d_in[1];
    const float* gat1_w   = (const float*)d_in[8];
    const float* gat1_as  = (const float*)d_in[9];
    const float* gat1_ad  = (const float*)d_in[10];
    const float* gat1_b   = (const float*)d_in[11];
    const float* gat1_res = (const float*)d_in[12];
    const float* gat2_w   = (const float*)d_in[13];
    const float* gat2_as  = (const float*)d_in[14];
    const float* gat2_ad  = (const float*)d_in[15];
    const float* gat2_b   = (const float*)d_in[16];
    const float* gat2_res = (const float*)d_in[17];
    const float* vlad_cw  = (const float*)d_in[18];
    const float* vlad_cb  = (const float*)d_in[19];
    const float* vlad_cw2 = (const float*)d_in[20];
    const float* vlad_h1w = (const float*)d_in[21];
    const float* vlad_h1b = (const float*)d_in[22];
    const float* gate_w   = (const float*)d_in[23];
    const float* gate_b   = (const float*)d_in[24];
    float* out = (float*)d_out;

    ptsgat1_kernel<<<2400, 256>>>(depth, gat1_w, gat1_as, gat1_ad, gat1_res);
    knn_kernel<<<600, 128>>>();
    attn_kernel<1, 128, true><<<2400, 256>>>(gat1_b);
    mm2_kernel<<<1200, 256>>>(gat2_w, gat2_res, gat2_as, gat2_ad);   // 4th: profiled
    attn_kernel<2, 256, false><<<2400, 256>>>(gat2_b);
    act_kernel<<<2400, 64>>>(vlad_cw, vlad_cb);
    vlad_partial<<<Bc * NCH, 1024>>>();
    vlad_finish<<<Bc * 64, 256>>>(vlad_cw2);
    y_partial<<<Bc * YCH, 256>>>(vlad_h1w);
    out_kernel<<<Bc, 256>>>(vlad_h1b, gate_w, gate_b, out);
}

// round 13
// speedup vs baseline: 1.3423x; 1.3423x over previous
#include <cuda_runtime.h>
#include <math.h>

#define Bc   2
#define Nc   9600
#define BNc  19200
#define Kc   10
#define DWc  150
#define PI_F 3.14159265358979323846f
#define NCH  75     // vlad N-chunks
#define CHN  128    // nodes per vlad chunk
#define YCH  64     // y-projection chunks
#define DEPTH    16 // knn push-buffer depth per thread
#define FLUSH_AT 8  // drain when any lane has >= FLUSH_AT pending (room for +8)

// ---------------- scratch (device-symbol access ONLY from device code) ----------------
__device__ float4 d_pts4[BNc];
__device__ int    d_edges[BNc * Kc];
__device__ float  d_h1[BNc * 128], d_res1[BNc * 128], d_g1[BNc * 128];
__device__ float  d_es[BNc], d_ed[BNc];
__device__ float  d_h2[BNc * 256], d_res2[BNc * 256], d_g2[BNc * 256];
__device__ float  d_act[BNc * 64];
__device__ float  d_vpart[Bc * NCH * 256 * 64];
__device__ float  d_vlad[Bc * 256 * 64];
__device__ float  d_colsq[Bc * 64];
__device__ float  d_ypart[Bc * YCH * 256];
__device__ float  d_nopbuf[4];

// ---------------- 0. nop (keeps knn as the 4th launch for ncu -s5-c1) ----------------
__global__ void nop_kernel(int which) {
    if ((int)blockIdx.x == (int)gridDim.x)   // never true; opaque to compiler
        d_nopbuf[which] = 1.0f;
}

// ---------------- 1+3a. fused: spherical->cartesian + GAT1 (3->128) ------------------
__global__ void ptsgat1_kernel(const float* __restrict__ depth,
                               const float* __restrict__ W,
                               const float* __restrict__ as_,
                               const float* __restrict__ ad_,
                               const float* __restrict__ RW)
{
    int gw   = (blockIdx.x * blockDim.x + threadIdx.x) >> 5;
    int lane = threadIdx.x & 31;
    if (gw >= BNc) return;

    int n = gw % Nc;
    int i = n / DWc;
    int j = n % DWc;
    float theta = -PI_F + (float)j * (2.0f * PI_F / 149.0f);
    float phi   = -0.5f * PI_F + (float)i * (PI_F / 63.0f);
    float r = depth[gw];
    float cp = cosf(phi), sp = sinf(phi);
    float st = sinf(theta), ct = cosf(theta);
    float px = r * cp * st;
    float py = r * sp;
    float pz = r * cp * ct;
    if (lane == 0)
        d_pts4[gw] = make_float4(px, py, pz, px * px + py * py + pz * pz);

    float e1 = 0.f, e2 = 0.f;
#pragma unroll
    for (int u = 0; u < 4; u++) {
        int c = lane + u * 32;
        float hv = px * W[c] + py * W[128 + c] + pz * W[256 + c];
        d_h1[gw * 128 + c]   = hv;
        d_res1[gw * 128 + c] = px * RW[c] + py * RW[128 + c] + pz * RW[256 + c];
        e1 += hv * as_[c];
        e2 += hv * ad_[c];
    }
#pragma unroll
    for (int o = 16; o > 0; o >>= 1) {
        e1 += __shfl_down_sync(0xffffffffu, e1, o);
        e2 += __shfl_down_sync(0xffffffffu, e2, o);
    }
    if (lane == 0) { d_es[gw] = e1; d_ed[gw] = e2; }
}

// exact strict-< sorted insert (keeps earlier index on ties)
#define CHAIN_INSERT(DV, IV)                                           \
    do {                                                               \
        bd[Kc - 1] = (DV); bi[Kc - 1] = (IV);                          \
        _Pragma("unroll")                                              \
        for (int s_ = Kc - 1; s_ > 0; --s_) {                          \
            if (bd[s_] < bd[s_ - 1]) {                                 \
                float td_ = bd[s_]; bd[s_] = bd[s_ - 1]; bd[s_ - 1] = td_; \
                int   ti_ = bi[s_]; bi[s_] = bi[s_ - 1]; bi[s_ - 1] = ti_; \
            }                                                          \
        }                                                              \
    } while (0)

// warp-uniform FIFO drain of push buffers through the exact chain
#define DRAIN()                                                        \
    do {                                                               \
        for (int j_ = 0; ; j_++) {                                     \
            if (!__ballot_sync(0xffffffffu, j_ < cnt)) break;          \
            if (j_ < cnt) {                                            \
                float2 e_ = sbuf[j_ * 256 + t];                        \
                if (e_.x < bd[Kc - 1])                                 \
                    CHAIN_INSERT(e_.x, __float_as_int(e_.y));          \
            }                                                          \
        }                                                              \
        cnt = 0;                                                       \
        pushThresh = fminf(pushThresh, bd[Kc - 1]);                    \
    } while (0)

// ---------------- 2. kNN (Round-11 version, verbatim: measured 252us) ----------------
// grid = 600, block = 256. 32 queries/block, 8 threads/query (partition = c mod 8).
__global__ void knn_kernel() {
    int b  = blockIdx.x / 300;
    int qb = blockIdx.x % 300;
    int t  = threadIdx.x;
    int ql = t >> 3;          // query within block (0..31)
    int h  = t & 7;           // candidate partition (c mod 8)
    int q  = qb * 32 + ql;
    int base = b * Nc;

    float4 qp = d_pts4[base + q];

    // pooled smem: stile | sbuf (reused as sval/sidx after final drain)
    __shared__ __align__(16) char pool[10240 + DEPTH * 256 * 8];
    float4* stile = (float4*)pool;                      // 640 * 16 = 10240 B
    float2* sbuf  = (float2*)(pool + 10240);            // 16*256*8 = 32768 B
    float*  sval  = (float*)(pool + 10240);             // overlays sbuf after drain
    int*    sidx  = (int*)(pool + 10240 + 10240);

    // ---- window pass: branchless values-only top-10 -> threshold T ----
    int wlo = q - 128;
    if (wlo < 0) wlo = 0;
    if (wlo > Nc - 256) wlo = Nc - 256;
    wlo &= ~7;
    float wd[Kc];
#pragma unroll
    for (int k = 0; k < Kc; k++) wd[k] = 3.4e38f;
#pragma unroll 4
    for (int j = 0; j < 32; j++) {
        int c = wlo + j * 8 + h;
        float4 p = d_pts4[base + c];
        float d2 = fmaf(-2.0f, fmaf(qp.x, p.x, fmaf(qp.y, p.y, qp.z * p.z)), p.w);
#pragma unroll
        for (int s = Kc - 1; s > 0; --s)
            wd[s] = fminf(wd[s], fmaxf(wd[s - 1], d2));
        wd[0] = fminf(wd[0], d2);
    }
    float pushThresh = wd[Kc - 1];

    float bd[Kc]; int bi[Kc];
#pragma unroll
    for (int k = 0; k < Kc; k++) { bd[k] = 3.4e38f; bi[k] = -1; }
    int cnt = 0;

    // ---- main scan: 15 tiles x 640; push candidates with s <= pushThresh ----
    for (int tile = 0; tile < 15; tile++) {
        int t0 = tile * 640;
        for (int i = t; i < 640; i += 256)
            stile[i] = d_pts4[base + t0 + i];
        __syncthreads();

        for (int cc = 0; cc < 80; cc += 8) {
            float sv[8];
#pragma unroll
            for (int u = 0; u < 8; u++) {
                float4 p = stile[(cc + u) * 8 + h];
                sv[u] = fmaf(-2.0f, fmaf(qp.x, p.x, fmaf(qp.y, p.y, qp.z * p.z)), p.w);
            }
            float m8 = fminf(fminf(fminf(sv[0], sv[1]), fminf(sv[2], sv[3])),
                             fminf(fminf(sv[4], sv[5]), fminf(sv[6], sv[7])));

            if (__ballot_sync(0xffffffffu, cnt >= FLUSH_AT)) DRAIN();

            if (m8 <= pushThresh) {          // arm = cheap appends only
#pragma unroll
                for (int u = 0; u < 8; u++) {
                    if (sv[u] <= pushThresh) {
                        sbuf[cnt * 256 + t] =
                            make_float2(sv[u], __int_as_float(t0 + (cc + u) * 8 + h));
                        cnt++;
                    }
                }
            }
        }
        __syncthreads();
    }

    DRAIN();
    __syncthreads();

    int lb = (ql * 8 + h) * Kc;
#pragma unroll
    for (int k = 0; k < Kc; k++) { sval[lb + k] = bd[k]; sidx[lb + k] = bi[k]; }
    __syncthreads();

    if (h == 0) {
        int p[8] = {0, 0, 0, 0, 0, 0, 0, 0};
        int lbase = ql * 8 * Kc;
#pragma unroll
        for (int outk = 0; outk < Kc; outk++) {
            float bv = 3.5e38f; int bix = 0x7fffffff; int bl = 0;
#pragma unroll
            for (int l = 0; l < 8; l++) {
                if (p[l] < Kc) {
                    float v = sval[lbase + l * Kc + p[l]];
                    int   ix = sidx[lbase + l * Kc + p[l]];
                    if (v < bv || (v == bv && ix < bix)) { bv = v; bix = ix; bl = l; }
                }
            }
            p[bl]++;
            d_edges[(base + q) * Kc + outk] = bix;
        }
    }
}

// ---------------- 3b. attention aggregate ----------------
template <int LAYER, int C, bool RELU>
__global__ void attn_kernel(const float* __restrict__ bias)
{
    const float* __restrict__ h   = (LAYER == 1) ? d_h1   : d_h2;
    const float* __restrict__ res = (LAYER == 1) ? d_res1 : d_res2;
    float* __restrict__ out       = (LAYER == 1) ? d_g1   : d_g2;

    int gw   = (blockIdx.x * blockDim.x + threadIdx.x) >> 5;
    int lane = threadIdx.x & 31;
    if (gw >= BNc) return;
    int b = gw / Nc;

    float edv = d_ed[gw];
    float lg[Kc];
    int   nb[Kc];
#pragma unroll
    for (int k = 0; k < Kc; k++) {
        nb[k] = b * Nc + d_edges[gw * Kc + k];
        float e = d_es[nb[k]] + edv;
        lg[k] = (e > 0.f) ? e : 0.2f * e;
    }
    float m = lg[0];
#pragma unroll
    for (int k = 1; k < Kc; k++) m = fmaxf(m, lg[k]);
    float sum = 0.f;
#pragma unroll
    for (int k = 0; k < Kc; k++) { lg[k] = expf(lg[k] - m); sum += lg[k]; }
    float inv = 1.0f / sum;

    for (int c = lane; c < C; c += 32) {
        float acc = 0.f;
#pragma unroll
        for (int k = 0; k < Kc; k++) acc += lg[k] * h[nb[k] * C + c];
        float v = acc * inv + bias[c] + res[gw * C + c];
        out[gw * C + c] = RELU ? fmaxf(v, 0.f) : v;
    }
}

// ---------------- 3c-1. GAT2 h-projection (128->256) + fused e_src/e_dst -------------
__global__ void mm2h_kernel(const float* __restrict__ W,
                            const float* __restrict__ as_,
                            const float* __restrict__ ad_)
{
    __shared__ float xs[16 * 128];
    __shared__ float wred[2][16][8];
    int nb0 = blockIdx.x * 16;
    int t = threadIdx.x;
    for (int i = t; i < 16 * 128; i += 256)
        xs[i] = d_g1[nb0 * 128 + i];
    __syncthreads();

    int c = t;
    float acc[16];
#pragma unroll
    for (int r = 0; r < 16; r++) acc[r] = 0.f;

    for (int i = 0; i < 128; i++) {
        float w = W[i * 256 + c];
#pragma unroll
        for (int r = 0; r < 16; r++)
            acc[r] += xs[r * 128 + i] * w;
    }

    float asv = as_[c], adv = ad_[c];
    int lane = t & 31, wid = t >> 5;
#pragma unroll
    for (int r = 0; r < 16; r++) {
        d_h2[(nb0 + r) * 256 + c] = acc[r];
        float v1 = acc[r] * asv;
        float v2 = acc[r] * adv;
#pragma unroll
        for (int o = 16; o > 0; o >>= 1) {
            v1 += __shfl_down_sync(0xffffffffu, v1, o);
            v2 += __shfl_down_sync(0xffffffffu, v2, o);
        }
        if (lane == 0) { wred[0][r][wid] = v1; wred[1][r][wid] = v2; }
    }
    __syncthreads();
    if (t < 32) {
        int r = t & 15, which = t >> 4;
        float s = 0.f;
#pragma unroll
        for (int w = 0; w < 8; w++) s += wred[which][r][w];
        if (which == 0) d_es[nb0 + r] = s;
        else            d_ed[nb0 + r] = s;
    }
}

// ---------------- 3c-2. GAT2 residual projection (128->256) --------------------------
__global__ void mm2r_kernel(const float* __restrict__ RW)
{
    __shared__ float xs[16 * 128];
    int nb0 = blockIdx.x * 16;
    int t = threadIdx.x;
    for (int i = t; i < 16 * 128; i += 256)
        xs[i] = d_g1[nb0 * 128 + i];
    __syncthreads();

    int c = t;
    float ar[16];
#pragma unroll
    for (int r = 0; r < 16; r++) ar[r] = 0.f;

    for (int i = 0; i < 128; i++) {
        float rw = RW[i * 256 + c];
#pragma unroll
        for (int r = 0; r < 16; r++)
            ar[r] += xs[r * 128 + i] * rw;
    }
#pragma unroll
    for (int r = 0; r < 16; r++)
        d_res2[(nb0 + r) * 256 + c] = ar[r];
}

// ---------------- 4a. NetVLAD cluster softmax ----------------
__global__ void act_kernel(const float* __restrict__ cw,
                           const float* __restrict__ cb)
{
    __shared__ float xs[8 * 256];
    __shared__ float red[64];
    int nb0 = blockIdx.x * 8;
    for (int i = threadIdx.x; i < 8 * 256; i += 64)
        xs[i] = d_g2[nb0 * 256 + i];
    __syncthreads();

    int k = threadIdx.x;
    float acc[8];
#pragma unroll
    for (int r = 0; r < 8; r++) acc[r] = cb[k];
    for (int dd = 0; dd < 256; dd++) {
        float w = cw[dd * 64 + k];
#pragma unroll
        for (int r = 0; r < 8; r++) acc[r] += xs[r * 256 + dd] * w;
    }

#pragma unroll
    for (int r = 0; r < 8; r++) {
        red[k] = acc[r];
        __syncthreads();
        for (int s = 32; s > 0; s >>= 1) {
            if (k < s) red[k] = fmaxf(red[k], red[k + s]);
            __syncthreads();
        }
        float m = red[0];
        __syncthreads();
        float e = expf(acc[r] - m);
        red[k] = e;
        __syncthreads();
        for (int s = 32; s > 0; s >>= 1) {
            if (k < s) red[k] += red[k + s];
            __syncthreads();
        }
        float sum = red[0];
        __syncthreads();
        d_act[(nb0 + r) * 64 + k] = e / sum;
    }
}

// ---------------- 4b. vlad partial ----------------
__global__ void vlad_partial() {
    int b  = blockIdx.x / NCH;
    int ch = blockIdx.x % NCH;
    int t  = threadIdx.x;
    int d  = t & 255;
    int kg = t >> 8;
    int base = b * Nc + ch * CHN;

    __shared__ float sact[16 * 64];
    float acc[16];
#pragma unroll
    for (int j = 0; j < 16; j++) acc[j] = 0.f;

    int nl = t >> 6, kk = t & 63;
    for (int n0 = 0; n0 < CHN; n0 += 16) {
        sact[t] = d_act[(base + n0 + nl) * 64 + kk];
        __syncthreads();
#pragma unroll
        for (int j = 0; j < 16; j++) {
            float g = d_g2[(base + n0 + j) * 256 + d];
            const float4* arow = (const float4*)&sact[j * 64 + kg * 16];
            float4 a0 = arow[0], a1 = arow[1], a2 = arow[2], a3 = arow[3];
            acc[0]  += g * a0.x; acc[1]  += g * a0.y; acc[2]  += g * a0.z; acc[3]  += g * a0.w;
            acc[4]  += g * a1.x; acc[5]  += g * a1.y; acc[6]  += g * a1.z; acc[7]  += g * a1.w;
            acc[8]  += g * a2.x; acc[9]  += g * a2.y; acc[10] += g * a2.z; acc[11] += g * a2.w;
            acc[12] += g * a3.x; acc[13] += g * a3.y; acc[14] += g * a3.z; acc[15] += g * a3.w;
        }
        __syncthreads();
    }

    float4* dst = (float4*)&d_vpart[(((b * NCH) + ch) * 256 + d) * 64 + kg * 16];
    dst[0] = make_float4(acc[0],  acc[1],  acc[2],  acc[3]);
    dst[1] = make_float4(acc[4],  acc[5],  acc[6],  acc[7]);
    dst[2] = make_float4(acc[8],  acc[9],  acc[10], acc[11]);
    dst[3] = make_float4(acc[12], acc[13], acc[14], acc[15]);
}

// ---------------- 4c. vlad finish ----------------
__global__ void vlad_finish(const float* __restrict__ cw2) {
    int b  = blockIdx.x >> 6;
    int k  = blockIdx.x & 63;
    int dd = threadIdx.x;

    float part = 0.f;
    for (int n = dd; n < Nc; n += 256)
        part += d_act[(b * Nc + n) * 64 + k];
    __shared__ float red[256];
    red[dd] = part;
    __syncthreads();
    for (int s = 128; s > 0; s >>= 1) {
        if (dd < s) red[dd] += red[dd + s];
        __syncthreads();
    }
    float asum = red[0];
    __syncthreads();

    float v = 0.f;
#pragma unroll 5
    for (int ch = 0; ch < NCH; ch++)
        v += d_vpart[((b * NCH + ch) * 256 + dd) * 64 + k];
    v -= asum * cw2[dd * 64 + k];

    red[dd] = v * v;
    __syncthreads();
    for (int s = 128; s > 0; s >>= 1) {
        if (dd < s) red[dd] += red[dd + s];
        __syncthreads();
    }
    float ss  = red[0];
    float den = fmaxf(sqrtf(ss), 1e-12f);
    d_vlad[(b * 256 + dd) * 64 + k] = v / den;
    if (dd == 0) d_colsq[b * 64 + k] = ss / (den * den);
}

// ---------------- 4d. y partial projection ----------------
__global__ void y_partial(const float* __restrict__ h1w) {
    int b  = blockIdx.x / YCH;
    int ch = blockIdx.x % YCH;
    int o  = threadIdx.x;
    __shared__ float sv[256];
    sv[o] = d_vlad[b * 16384 + ch * 256 + o];
    __syncthreads();
    float acc = 0.f;
#pragma unroll 4
    for (int j = 0; j < 256; j++)
        acc += sv[j] * h1w[(ch * 256 + j) * 256 + o];
    d_ypart[(b * YCH + ch) * 256 + o] = acc;
}

// ---------------- 4e. reduce y + gate + output ----------------
__global__ void out_kernel(const float* __restrict__ h1b,
                           const float* __restrict__ gw,
                           const float* __restrict__ gb,
                           float* __restrict__ out)
{
    int b = blockIdx.x;
    int o = threadIdx.x;
    __shared__ float sc[64];
    __shared__ float gs;
    if (o < 64) sc[o] = d_colsq[b * 64 + o];
    __syncthreads();
    if (o == 0) {
        float s = 0.f;
        for (int i = 0; i < 64; i++) s += sc[i];
        gs = 1.0f / fmaxf(sqrtf(s), 1e-12f);
    }
    __syncthreads();

    float acc = 0.f;
#pragma unroll
    for (int ch = 0; ch < YCH; ch++)
        acc += d_ypart[(b * YCH + ch) * 256 + o];
    float y = acc * gs + h1b[o];

    __shared__ float sy[256];
    sy[o] = y;
    __syncthreads();
    float g = gb[o];
    for (int j = 0; j < 256; j++) g += sy[j] * gw[j * 256 + o];
    out[b * 256 + o] = y * (1.0f / (1.0f + expf(-g)));
}

// ---------------- launch ----------------
extern "C" void kernel_launch(void* const* d_in, const int* in_sizes, int n_in,
                              void* d_out, int out_size) {
    const float* depth    = (const float*)d_in[1];
    const float* gat1_w   = (const float*)d_in[8];
    const float* gat1_as  = (const float*)d_in[9];
    const float* gat1_ad  = (const float*)d_in[10];
    const float* gat1_b   = (const float*)d_in[11];
    const float* gat1_res = (const float*)d_in[12];
    const float* gat2_w   = (const float*)d_in[13];
    const float* gat2_as  = (const float*)d_in[14];
    const float* gat2_ad  = (const float*)d_in[15];
    const float* gat2_b   = (const float*)d_in[16];
    const float* gat2_res = (const float*)d_in[17];
    const float* vlad_cw  = (const float*)d_in[18];
    const float* vlad_cb  = (const float*)d_in[19];
    const float* vlad_cw2 = (const float*)d_in[20];
    const float* vlad_h1w = (const float*)d_in[21];
    const float* vlad_h1b = (const float*)d_in[22];
    const float* gate_w   = (const float*)d_in[23];
    const float* gate_b   = (const float*)d_in[24];
    float* out = (float*)d_out;

    ptsgat1_kernel<<<2400, 256>>>(depth, gat1_w, gat1_as, gat1_ad, gat1_res);
    nop_kernel<<<1, 32>>>(0);            // keep knn as 4th launch for ncu
    nop_kernel<<<1, 32>>>(1);
    knn_kernel<<<600, 256>>>();
    attn_kernel<1, 128, true><<<2400, 256>>>(gat1_b);
    mm2h_kernel<<<1200, 256>>>(gat2_w, gat2_as, gat2_ad);
    mm2r_kernel<<<1200, 256>>>(gat2_res);
    attn_kernel<2, 256, false><<<2400, 256>>>(gat2_b);
    act_kernel<<<2400, 64>>>(vlad_cw, vlad_cb);
    vlad_partial<<<Bc * NCH, 1024>>>();
    vlad_finish<<<Bc * 64, 256>>>(vlad_cw2);
    y_partial<<<Bc * YCH, 256>>>(vlad_h1w);
    out_kernel<<<Bc, 256>>>(vlad_h1b, gate_w, gate_b, out);
}

// round 14
// speedup vs baseline: 1.3730x; 1.0229x over previous
#include <cuda_runtime.h>
#include <math.h>

#define Bc   2
#define Nc   9600
#define BNc  19200
#define Kc   10
#define DWc  150
#define PI_F 3.14159265358979323846f
#define NCH  75     // vlad N-chunks
#define CHN  128    // nodes per vlad chunk
#define YCH  64     // y-projection chunks
#define DEPTH    12 // knn push-buffer depth per thread (smem diet -> 4 blocks/SM)
#define FLUSH_AT 4  // drain when any lane has >= FLUSH_AT pending (room for +8)

// ---------------- scratch (device-symbol access ONLY from device code) ----------------
__device__ float4 d_pts4[BNc];
__device__ int    d_edges[BNc * Kc];
__device__ float  d_h1[BNc * 128], d_res1[BNc * 128], d_g1[BNc * 128];
__device__ float  d_es[BNc], d_ed[BNc];
__device__ float  d_h2[BNc * 256], d_res2[BNc * 256], d_g2[BNc * 256];
__device__ float  d_act[BNc * 64];
__device__ float  d_vpart[Bc * NCH * 256 * 64];
__device__ float  d_vlad[Bc * 256 * 64];
__device__ float  d_colsq[Bc * 64];
__device__ float  d_ypart[Bc * YCH * 256];
__device__ float  d_nopbuf[4];

// ---------------- 0. nop (keeps knn as the 4th launch for ncu -s5-c1) ----------------
__global__ void nop_kernel(int which) {
    if ((int)blockIdx.x == (int)gridDim.x)   // never true; opaque to compiler
        d_nopbuf[which] = 1.0f;
}

// ---------------- 1+3a. fused: spherical->cartesian + GAT1 (3->128) ------------------
__global__ void ptsgat1_kernel(const float* __restrict__ depth,
                               const float* __restrict__ W,
                               const float* __restrict__ as_,
                               const float* __restrict__ ad_,
                               const float* __restrict__ RW)
{
    int gw   = (blockIdx.x * blockDim.x + threadIdx.x) >> 5;
    int lane = threadIdx.x & 31;
    if (gw >= BNc) return;

    int n = gw % Nc;
    int i = n / DWc;
    int j = n % DWc;
    float theta = -PI_F + (float)j * (2.0f * PI_F / 149.0f);
    float phi   = -0.5f * PI_F + (float)i * (PI_F / 63.0f);
    float r = depth[gw];
    float cp = cosf(phi), sp = sinf(phi);
    float st = sinf(theta), ct = cosf(theta);
    float px = r * cp * st;
    float py = r * sp;
    float pz = r * cp * ct;
    if (lane == 0)
        d_pts4[gw] = make_float4(px, py, pz, px * px + py * py + pz * pz);

    float e1 = 0.f, e2 = 0.f;
#pragma unroll
    for (int u = 0; u < 4; u++) {
        int c = lane + u * 32;
        float hv = px * W[c] + py * W[128 + c] + pz * W[256 + c];
        d_h1[gw * 128 + c]   = hv;
        d_res1[gw * 128 + c] = px * RW[c] + py * RW[128 + c] + pz * RW[256 + c];
        e1 += hv * as_[c];
        e2 += hv * ad_[c];
    }
#pragma unroll
    for (int o = 16; o > 0; o >>= 1) {
        e1 += __shfl_down_sync(0xffffffffu, e1, o);
        e2 += __shfl_down_sync(0xffffffffu, e2, o);
    }
    if (lane == 0) { d_es[gw] = e1; d_ed[gw] = e2; }
}

// exact strict-< sorted insert (keeps earlier index on ties)
#define CHAIN_INSERT(DV, IV)                                           \
    do {                                                               \
        bd[Kc - 1] = (DV); bi[Kc - 1] = (IV);                          \
        _Pragma("unroll")                                              \
        for (int s_ = Kc - 1; s_ > 0; --s_) {                          \
            if (bd[s_] < bd[s_ - 1]) {                                 \
                float td_ = bd[s_]; bd[s_] = bd[s_ - 1]; bd[s_ - 1] = td_; \
                int   ti_ = bi[s_]; bi[s_] = bi[s_ - 1]; bi[s_ - 1] = ti_; \
            }                                                          \
        }                                                              \
    } while (0)

// warp-uniform FIFO drain of push buffers through the exact chain
#define DRAIN()                                                        \
    do {                                                               \
        for (int j_ = 0; ; j_++) {                                     \
            if (!__ballot_sync(0xffffffffu, j_ < cnt)) break;          \
            if (j_ < cnt) {                                            \
                float2 e_ = sbuf[j_ * 256 + t];                        \
                if (e_.x < bd[Kc - 1])                                 \
                    CHAIN_INSERT(e_.x, __float_as_int(e_.y));          \
            }                                                          \
        }                                                              \
        cnt = 0;                                                       \
        pushThresh = fminf(pushThresh, bd[Kc - 1]);                    \
    } while (0)

// ---------------- 2. kNN (R11 structure, DEPTH=12 for 4 blocks/SM) --------------------
// grid = 600, block = 256. 32 queries/block, 8 threads/query (partition = c mod 8).
__global__ void knn_kernel() {
    int b  = blockIdx.x / 300;
    int qb = blockIdx.x % 300;
    int t  = threadIdx.x;
    int ql = t >> 3;          // query within block (0..31)
    int h  = t & 7;           // candidate partition (c mod 8)
    int q  = qb * 32 + ql;
    int base = b * Nc;

    float4 qp = d_pts4[base + q];

    // pooled smem: stile | sbuf (reused as sval/sidx after final drain)
    __shared__ __align__(16) char pool[10240 + DEPTH * 256 * 8];
    float4* stile = (float4*)pool;                      // 640 * 16 = 10240 B
    float2* sbuf  = (float2*)(pool + 10240);            // 12*256*8 = 24576 B
    float*  sval  = (float*)(pool + 10240);             // overlays sbuf after drain
    int*    sidx  = (int*)(pool + 10240 + 10240);

    // ---- window pass: branchless values-only top-10 -> threshold T ----
    int wlo = q - 128;
    if (wlo < 0) wlo = 0;
    if (wlo > Nc - 256) wlo = Nc - 256;
    wlo &= ~7;
    float wd[Kc];
#pragma unroll
    for (int k = 0; k < Kc; k++) wd[k] = 3.4e38f;
#pragma unroll 4
    for (int j = 0; j < 32; j++) {
        int c = wlo + j * 8 + h;
        float4 p = d_pts4[base + c];
        float d2 = fmaf(-2.0f, fmaf(qp.x, p.x, fmaf(qp.y, p.y, qp.z * p.z)), p.w);
#pragma unroll
        for (int s = Kc - 1; s > 0; --s)
            wd[s] = fminf(wd[s], fmaxf(wd[s - 1], d2));
        wd[0] = fminf(wd[0], d2);
    }
    float pushThresh = wd[Kc - 1];

    float bd[Kc]; int bi[Kc];
#pragma unroll
    for (int k = 0; k < Kc; k++) { bd[k] = 3.4e38f; bi[k] = -1; }
    int cnt = 0;

    // ---- main scan: 15 tiles x 640; push candidates with s <= pushThresh ----
    for (int tile = 0; tile < 15; tile++) {
        int t0 = tile * 640;
        for (int i = t; i < 640; i += 256)
            stile[i] = d_pts4[base + t0 + i];
        __syncthreads();

        for (int cc = 0; cc < 80; cc += 8) {
            float sv[8];
#pragma unroll
            for (int u = 0; u < 8; u++) {
                float4 p = stile[(cc + u) * 8 + h];
                sv[u] = fmaf(-2.0f, fmaf(qp.x, p.x, fmaf(qp.y, p.y, qp.z * p.z)), p.w);
            }
            float m8 = fminf(fminf(fminf(sv[0], sv[1]), fminf(sv[2], sv[3])),
                             fminf(fminf(sv[4], sv[5]), fminf(sv[6], sv[7])));

            if (__ballot_sync(0xffffffffu, cnt >= FLUSH_AT)) DRAIN();

            if (m8 <= pushThresh) {          // arm = cheap appends only
#pragma unroll
                for (int u = 0; u < 8; u++) {
                    if (sv[u] <= pushThresh) {
                        sbuf[cnt * 256 + t] =
                            make_float2(sv[u], __int_as_float(t0 + (cc + u) * 8 + h));
                        cnt++;
                    }
                }
            }
        }
        __syncthreads();
    }

    DRAIN();
    __syncthreads();

    int lb = (ql * 8 + h) * Kc;
#pragma unroll
    for (int k = 0; k < Kc; k++) { sval[lb + k] = bd[k]; sidx[lb + k] = bi[k]; }
    __syncthreads();

    if (h == 0) {
        int p[8] = {0, 0, 0, 0, 0, 0, 0, 0};
        int lbase = ql * 8 * Kc;
#pragma unroll
        for (int outk = 0; outk < Kc; outk++) {
            float bv = 3.5e38f; int bix = 0x7fffffff; int bl = 0;
#pragma unroll
            for (int l = 0; l < 8; l++) {
                if (p[l] < Kc) {
                    float v = sval[lbase + l * Kc + p[l]];
                    int   ix = sidx[lbase + l * Kc + p[l]];
                    if (v < bv || (v == bv && ix < bix)) { bv = v; bix = ix; bl = l; }
                }
            }
            p[bl]++;
            d_edges[(base + q) * Kc + outk] = bix;
        }
    }
}

// ---------------- 3b. attention aggregate ----------------
template <int LAYER, int C, bool RELU>
__global__ void attn_kernel(const float* __restrict__ bias)
{
    const float* __restrict__ h   = (LAYER == 1) ? d_h1   : d_h2;
    const float* __restrict__ res = (LAYER == 1) ? d_res1 : d_res2;
    float* __restrict__ out       = (LAYER == 1) ? d_g1   : d_g2;

    int gw   = (blockIdx.x * blockDim.x + threadIdx.x) >> 5;
    int lane = threadIdx.x & 31;
    if (gw >= BNc) return;
    int b = gw / Nc;

    float edv = d_ed[gw];
    float lg[Kc];
    int   nb[Kc];
#pragma unroll
    for (int k = 0; k < Kc; k++) {
        nb[k] = b * Nc + d_edges[gw * Kc + k];
        float e = d_es[nb[k]] + edv;
        lg[k] = (e > 0.f) ? e : 0.2f * e;
    }
    float m = lg[0];
#pragma unroll
    for (int k = 1; k < Kc; k++) m = fmaxf(m, lg[k]);
    float sum = 0.f;
#pragma unroll
    for (int k = 0; k < Kc; k++) { lg[k] = expf(lg[k] - m); sum += lg[k]; }
    float inv = 1.0f / sum;

    for (int c = lane; c < C; c += 32) {
        float acc = 0.f;
#pragma unroll
        for (int k = 0; k < Kc; k++) acc += lg[k] * h[nb[k] * C + c];
        float v = acc * inv + bias[c] + res[gw * C + c];
        out[gw * C + c] = RELU ? fmaxf(v, 0.f) : v;
    }
}

// ---------------- 3c. GAT2 matmul (128->256), 16 nodes/block, fused e_src/e_dst ------
// (R11 fused version: weights read once; measured 93us)
__global__ void mm2_kernel(const float* __restrict__ W,
                           const float* __restrict__ RW,
                           const float* __restrict__ as_,
                           const float* __restrict__ ad_)
{
    __shared__ float xs[16 * 128];
    __shared__ float wred[2][16][8];
    int nb0 = blockIdx.x * 16;
    int t = threadIdx.x;
    for (int i = t; i < 16 * 128; i += 256)
        xs[i] = d_g1[nb0 * 128 + i];
    __syncthreads();

    int c = t;
    float acc[16], ar[16];
#pragma unroll
    for (int r = 0; r < 16; r++) { acc[r] = 0.f; ar[r] = 0.f; }

    for (int i = 0; i < 128; i++) {
        float w  = W[i * 256 + c];
        float rw = RW[i * 256 + c];
#pragma unroll
        for (int r = 0; r < 16; r++) {
            float xv = xs[r * 128 + i];
            acc[r] += xv * w;
            ar[r]  += xv * rw;
        }
    }

    float asv = as_[c], adv = ad_[c];
    int lane = t & 31, wid = t >> 5;
#pragma unroll
    for (int r = 0; r < 16; r++) {
        d_h2[(nb0 + r) * 256 + c]   = acc[r];
        d_res2[(nb0 + r) * 256 + c] = ar[r];
        float v1 = acc[r] * asv;
        float v2 = acc[r] * adv;
#pragma unroll
        for (int o = 16; o > 0; o >>= 1) {
            v1 += __shfl_down_sync(0xffffffffu, v1, o);
            v2 += __shfl_down_sync(0xffffffffu, v2, o);
        }
        if (lane == 0) { wred[0][r][wid] = v1; wred[1][r][wid] = v2; }
    }
    __syncthreads();
    if (t < 32) {
        int r = t & 15, which = t >> 4;
        float s = 0.f;
#pragma unroll
        for (int w = 0; w < 8; w++) s += wred[which][r][w];
        if (which == 0) d_es[nb0 + r] = s;
        else            d_ed[nb0 + r] = s;
    }
}

// ---------------- 4a. NetVLAD cluster softmax ----------------
__global__ void act_kernel(const float* __restrict__ cw,
                           const float* __restrict__ cb)
{
    __shared__ float xs[8 * 256];
    __shared__ float red[64];
    int nb0 = blockIdx.x * 8;
    for (int i = threadIdx.x; i < 8 * 256; i += 64)
        xs[i] = d_g2[nb0 * 256 + i];
    __syncthreads();

    int k = threadIdx.x;
    float acc[8];
#pragma unroll
    for (int r = 0; r < 8; r++) acc[r] = cb[k];
    for (int dd = 0; dd < 256; dd++) {
        float w = cw[dd * 64 + k];
#pragma unroll
        for (int r = 0; r < 8; r++) acc[r] += xs[r * 256 + dd] * w;
    }

#pragma unroll
    for (int r = 0; r < 8; r++) {
        red[k] = acc[r];
        __syncthreads();
        for (int s = 32; s > 0; s >>= 1) {
            if (k < s) red[k] = fmaxf(red[k], red[k + s]);
            __syncthreads();
        }
        float m = red[0];
        __syncthreads();
        float e = expf(acc[r] - m);
        red[k] = e;
        __syncthreads();
        for (int s = 32; s > 0; s >>= 1) {
            if (k < s) red[k] += red[k + s];
            __syncthreads();
        }
        float sum = red[0];
        __syncthreads();
        d_act[(nb0 + r) * 64 + k] = e / sum;
    }
}

// ---------------- 4b. vlad partial ----------------
__global__ void vlad_partial() {
    int b  = blockIdx.x / NCH;
    int ch = blockIdx.x % NCH;
    int t  = threadIdx.x;
    int d  = t & 255;
    int kg = t >> 8;
    int base = b * Nc + ch * CHN;

    __shared__ float sact[16 * 64];
    float acc[16];
#pragma unroll
    for (int j = 0; j < 16; j++) acc[j] = 0.f;

    int nl = t >> 6, kk = t & 63;
    for (int n0 = 0; n0 < CHN; n0 += 16) {
        sact[t] = d_act[(base + n0 + nl) * 64 + kk];
        __syncthreads();
#pragma unroll
        for (int j = 0; j < 16; j++) {
            float g = d_g2[(base + n0 + j) * 256 + d];
            const float4* arow = (const float4*)&sact[j * 64 + kg * 16];
            float4 a0 = arow[0], a1 = arow[1], a2 = arow[2], a3 = arow[3];
            acc[0]  += g * a0.x; acc[1]  += g * a0.y; acc[2]  += g * a0.z; acc[3]  += g * a0.w;
            acc[4]  += g * a1.x; acc[5]  += g * a1.y; acc[6]  += g * a1.z; acc[7]  += g * a1.w;
            acc[8]  += g * a2.x; acc[9]  += g * a2.y; acc[10] += g * a2.z; acc[11] += g * a2.w;
            acc[12] += g * a3.x; acc[13] += g * a3.y; acc[14] += g * a3.z; acc[15] += g * a3.w;
        }
        __syncthreads();
    }

    float4* dst = (float4*)&d_vpart[(((b * NCH) + ch) * 256 + d) * 64 + kg * 16];
    dst[0] = make_float4(acc[0],  acc[1],  acc[2],  acc[3]);
    dst[1] = make_float4(acc[4],  acc[5],  acc[6],  acc[7]);
    dst[2] = make_float4(acc[8],  acc[9],  acc[10], acc[11]);
    dst[3] = make_float4(acc[12], acc[13], acc[14], acc[15]);
}

// ---------------- 4c. vlad finish ----------------
__global__ void vlad_finish(const float* __restrict__ cw2) {
    int b  = blockIdx.x >> 6;
    int k  = blockIdx.x & 63;
    int dd = threadIdx.x;

    float part = 0.f;
    for (int n = dd; n < Nc; n += 256)
        part += d_act[(b * Nc + n) * 64 + k];
    __shared__ float red[256];
    red[dd] = part;
    __syncthreads();
    for (int s = 128; s > 0; s >>= 1) {
        if (dd < s) red[dd] += red[dd + s];
        __syncthreads();
    }
    float asum = red[0];
    __syncthreads();

    float v = 0.f;
#pragma unroll 5
    for (int ch = 0; ch < NCH; ch++)
        v += d_vpart[((b * NCH + ch) * 256 + dd) * 64 + k];
    v -= asum * cw2[dd * 64 + k];

    red[dd] = v * v;
    __syncthreads();
    for (int s = 128; s > 0; s >>= 1) {
        if (dd < s) red[dd] += red[dd + s];
        __syncthreads();
    }
    float ss  = red[0];
    float den = fmaxf(sqrtf(ss), 1e-12f);
    d_vlad[(b * 256 + dd) * 64 + k] = v / den;
    if (dd == 0) d_colsq[b * 64 + k] = ss / (den * den);
}

// ---------------- 4d. y partial projection ----------------
__global__ void y_partial(const float* __restrict__ h1w) {
    int b  = blockIdx.x / YCH;
    int ch = blockIdx.x % YCH;
    int o  = threadIdx.x;
    __shared__ float sv[256];
    sv[o] = d_vlad[b * 16384 + ch * 256 + o];
    __syncthreads();
    float acc = 0.f;
#pragma unroll 4
    for (int j = 0; j < 256; j++)
        acc += sv[j] * h1w[(ch * 256 + j) * 256 + o];
    d_ypart[(b * YCH + ch) * 256 + o] = acc;
}

// ---------------- 4e. reduce y + gate + output ----------------
__global__ void out_kernel(const float* __restrict__ h1b,
                           const float* __restrict__ gw,
                           const float* __restrict__ gb,
                           float* __restrict__ out)
{
    int b = blockIdx.x;
    int o = threadIdx.x;
    __shared__ float sc[64];
    __shared__ float gs;
    if (o < 64) sc[o] = d_colsq[b * 64 + o];
    __syncthreads();
    if (o == 0) {
        float s = 0.f;
        for (int i = 0; i < 64; i++) s += sc[i];
        gs = 1.0f / fmaxf(sqrtf(s), 1e-12f);
    }
    __syncthreads();

    float acc = 0.f;
#pragma unroll
    for (int ch = 0; ch < YCH; ch++)
        acc += d_ypart[(b * YCH + ch) * 256 + o];
    float y = acc * gs + h1b[o];

    __shared__ float sy[256];
    sy[o] = y;
    __syncthreads();
    float g = gb[o];
    for (int j = 0; j < 256; j++) g += sy[j] * gw[j * 256 + o];
    out[b * 256 + o] = y * (1.0f / (1.0f + expf(-g)));
}

// ---------------- launch ----------------
extern "C" void kernel_launch(void* const* d_in, const int* in_sizes, int n_in,
                              void* d_out, int out_size) {
    const float* depth    = (const float*)d_in[1];
    const float* gat1_w   = (const float*)d_in[8];
    const float* gat1_as  = (const float*)d_in[9];
    const float* gat1_ad  = (const float*)d_in[10];
    const float* gat1_b   = (const float*)d_in[11];
    const float* gat1_res = (const float*)d_in[12];
    const float* gat2_w   = (const float*)d_in[13];
    const float* gat2_as  = (const float*)d_in[14];
    const float* gat2_ad  = (const float*)d_in[15];
    const float* gat2_b   = (const float*)d_in[16];
    const float* gat2_res = (const float*)d_in[17];
    const float* vlad_cw  = (const float*)d_in[18];
    const float* vlad_cb  = (const float*)d_in[19];
    const float* vlad_cw2 = (const float*)d_in[20];
    const float* vlad_h1w = (const float*)d_in[21];
    const float* vlad_h1b = (const float*)d_in[22];
    const float* gate_w   = (const float*)d_in[23];
    const float* gate_b   = (const float*)d_in[24];
    float* out = (float*)d_out;

    ptsgat1_kernel<<<2400, 256>>>(depth, gat1_w, gat1_as, gat1_ad, gat1_res);
    nop_kernel<<<1, 32>>>(0);            // keep knn as 4th launch for ncu
    nop_kernel<<<1, 32>>>(1);
    knn_kernel<<<600, 256>>>();
    attn_kernel<1, 128, true><<<2400, 256>>>(gat1_b);
    mm2_kernel<<<1200, 256>>>(gat2_w, gat2_res, gat2_as, gat2_ad);
    attn_kernel<2, 256, false><<<2400, 256>>>(gat2_b);
    act_kernel<<<2400, 64>>>(vlad_cw, vlad_cb);
    vlad_partial<<<Bc * NCH, 1024>>>();
    vlad_finish<<<Bc * 64, 256>>>(vlad_cw2);
    y_partial<<<Bc * YCH, 256>>>(vlad_h1w);
    out_kernel<<<Bc, 256>>>(vlad_h1b, gate_w, gate_b, out);
}

// round 15
// speedup vs baseline: 1.4317x; 1.0427x over previous
#include <cuda_runtime.h>
#include <math.h>

#define Bc   2
#define Nc   9600
#define BNc  19200
#define Kc   10
#define DWc  150
#define PI_F 3.14159265358979323846f
#define NCH  75     // vlad N-chunks
#define CHN  128    // nodes per vlad chunk
#define YCH  64     // y-projection chunks
#define DEPTH    16 // knn push-buffer depth per thread (R11 measured-best)
#define FLUSH_AT 8  // drain when any lane has >= FLUSH_AT pending (room for +8)

// ---------------- scratch (device-symbol access ONLY from device code) ----------------
__device__ float4 d_pts4[BNc];
__device__ int    d_edges[BNc * Kc];
__device__ float  d_h1[BNc * 128], d_res1[BNc * 128], d_g1[BNc * 128];
__device__ float  d_es[BNc], d_ed[BNc];
__device__ float  d_h2[BNc * 256], d_res2[BNc * 256], d_g2[BNc * 256];
__device__ float  d_act[BNc * 64];
__device__ float  d_vpart[Bc * NCH * 256 * 64];
__device__ float  d_vlad[Bc * 256 * 64];
__device__ float  d_colsq[Bc * 64];
__device__ float  d_ypart[Bc * YCH * 256];
__device__ float  d_nopbuf[4];

// ---------------- 0. nop (keeps knn as the 4th launch for ncu -s5-c1) ----------------
__global__ void nop_kernel(int which) {
    if ((int)blockIdx.x == (int)gridDim.x)   // never true; opaque to compiler
        d_nopbuf[which] = 1.0f;
}

// ---------------- 1+3a. fused: spherical->cartesian + GAT1 (3->128) ------------------
__global__ void ptsgat1_kernel(const float* __restrict__ depth,
                               const float* __restrict__ W,
                               const float* __restrict__ as_,
                               const float* __restrict__ ad_,
                               const float* __restrict__ RW)
{
    int gw   = (blockIdx.x * blockDim.x + threadIdx.x) >> 5;
    int lane = threadIdx.x & 31;
    if (gw >= BNc) return;

    int n = gw % Nc;
    int i = n / DWc;
    int j = n % DWc;
    float theta = -PI_F + (float)j * (2.0f * PI_F / 149.0f);
    float phi   = -0.5f * PI_F + (float)i * (PI_F / 63.0f);
    float r = depth[gw];
    float cp = cosf(phi), sp = sinf(phi);
    float st = sinf(theta), ct = cosf(theta);
    float px = r * cp * st;
    float py = r * sp;
    float pz = r * cp * ct;
    if (lane == 0)
        d_pts4[gw] = make_float4(px, py, pz, px * px + py * py + pz * pz);

    float e1 = 0.f, e2 = 0.f;
#pragma unroll
    for (int u = 0; u < 4; u++) {
        int c = lane + u * 32;
        float hv = px * W[c] + py * W[128 + c] + pz * W[256 + c];
        d_h1[gw * 128 + c]   = hv;
        d_res1[gw * 128 + c] = px * RW[c] + py * RW[128 + c] + pz * RW[256 + c];
        e1 += hv * as_[c];
        e2 += hv * ad_[c];
    }
#pragma unroll
    for (int o = 16; o > 0; o >>= 1) {
        e1 += __shfl_down_sync(0xffffffffu, e1, o);
        e2 += __shfl_down_sync(0xffffffffu, e2, o);
    }
    if (lane == 0) { d_es[gw] = e1; d_ed[gw] = e2; }
}

// exact strict-< sorted insert (keeps earlier index on ties)
#define CHAIN_INSERT(DV, IV)                                           \
    do {                                                               \
        bd[Kc - 1] = (DV); bi[Kc - 1] = (IV);                          \
        _Pragma("unroll")                                              \
        for (int s_ = Kc - 1; s_ > 0; --s_) {                          \
            if (bd[s_] < bd[s_ - 1]) {                                 \
                float td_ = bd[s_]; bd[s_] = bd[s_ - 1]; bd[s_ - 1] = td_; \
                int   ti_ = bi[s_]; bi[s_] = bi[s_ - 1]; bi[s_ - 1] = ti_; \
            }                                                          \
        }                                                              \
    } while (0)

// warp-uniform FIFO drain of push buffers through the exact chain
#define DRAIN()                                                        \
    do {                                                               \
        for (int j_ = 0; ; j_++) {                                     \
            if (!__ballot_sync(0xffffffffu, j_ < cnt)) break;          \
            if (j_ < cnt) {                                            \
                float2 e_ = sbuf[j_ * 256 + t];                        \
                if (e_.x < bd[Kc - 1])                                 \
                    CHAIN_INSERT(e_.x, __float_as_int(e_.y));          \
            }                                                          \
        }                                                              \
        cnt = 0;                                                       \
        pushThresh = fminf(pushThresh, bd[Kc - 1]);                    \
    } while (0)

// ---------------- 2. kNN (Round-11 version, verbatim: measured 252us) ----------------
__global__ void knn_kernel() {
    int b  = blockIdx.x / 300;
    int qb = blockIdx.x % 300;
    int t  = threadIdx.x;
    int ql = t >> 3;          // query within block (0..31)
    int h  = t & 7;           // candidate partition (c mod 8)
    int q  = qb * 32 + ql;
    int base = b * Nc;

    float4 qp = d_pts4[base + q];

    __shared__ __align__(16) char pool[10240 + DEPTH * 256 * 8];
    float4* stile = (float4*)pool;                      // 640 * 16 = 10240 B
    float2* sbuf  = (float2*)(pool + 10240);            // 16*256*8 = 32768 B
    float*  sval  = (float*)(pool + 10240);             // overlays sbuf after drain
    int*    sidx  = (int*)(pool + 10240 + 10240);

    int wlo = q - 128;
    if (wlo < 0) wlo = 0;
    if (wlo > Nc - 256) wlo = Nc - 256;
    wlo &= ~7;
    float wd[Kc];
#pragma unroll
    for (int k = 0; k < Kc; k++) wd[k] = 3.4e38f;
#pragma unroll 4
    for (int j = 0; j < 32; j++) {
        int c = wlo + j * 8 + h;
        float4 p = d_pts4[base + c];
        float d2 = fmaf(-2.0f, fmaf(qp.x, p.x, fmaf(qp.y, p.y, qp.z * p.z)), p.w);
#pragma unroll
        for (int s = Kc - 1; s > 0; --s)
            wd[s] = fminf(wd[s], fmaxf(wd[s - 1], d2));
        wd[0] = fminf(wd[0], d2);
    }
    float pushThresh = wd[Kc - 1];

    float bd[Kc]; int bi[Kc];
#pragma unroll
    for (int k = 0; k < Kc; k++) { bd[k] = 3.4e38f; bi[k] = -1; }
    int cnt = 0;

    for (int tile = 0; tile < 15; tile++) {
        int t0 = tile * 640;
        for (int i = t; i < 640; i += 256)
            stile[i] = d_pts4[base + t0 + i];
        __syncthreads();

        for (int cc = 0; cc < 80; cc += 8) {
            float sv[8];
#pragma unroll
            for (int u = 0; u < 8; u++) {
                float4 p = stile[(cc + u) * 8 + h];
                sv[u] = fmaf(-2.0f, fmaf(qp.x, p.x, fmaf(qp.y, p.y, qp.z * p.z)), p.w);
            }
            float m8 = fminf(fminf(fminf(sv[0], sv[1]), fminf(sv[2], sv[3])),
                             fminf(fminf(sv[4], sv[5]), fminf(sv[6], sv[7])));

            if (__ballot_sync(0xffffffffu, cnt >= FLUSH_AT)) DRAIN();

            if (m8 <= pushThresh) {
#pragma unroll
                for (int u = 0; u < 8; u++) {
                    if (sv[u] <= pushThresh) {
                        sbuf[cnt * 256 + t] =
                            make_float2(sv[u], __int_as_float(t0 + (cc + u) * 8 + h));
                        cnt++;
                    }
                }
            }
        }
        __syncthreads();
    }

    DRAIN();
    __syncthreads();

    int lb = (ql * 8 + h) * Kc;
#pragma unroll
    for (int k = 0; k < Kc; k++) { sval[lb + k] = bd[k]; sidx[lb + k] = bi[k]; }
    __syncthreads();

    if (h == 0) {
        int p[8] = {0, 0, 0, 0, 0, 0, 0, 0};
        int lbase = ql * 8 * Kc;
#pragma unroll
        for (int outk = 0; outk < Kc; outk++) {
            float bv = 3.5e38f; int bix = 0x7fffffff; int bl = 0;
#pragma unroll
            for (int l = 0; l < 8; l++) {
                if (p[l] < Kc) {
                    float v = sval[lbase + l * Kc + p[l]];
                    int   ix = sidx[lbase + l * Kc + p[l]];
                    if (v < bv || (v == bv && ix < bix)) { bv = v; bix = ix; bl = l; }
                }
            }
            p[bl]++;
            d_edges[(base + q) * Kc + outk] = bix;
        }
    }
}

// ---------------- 3b. attention aggregate ----------------
template <int LAYER, int C, bool RELU>
__global__ void attn_kernel(const float* __restrict__ bias)
{
    const float* __restrict__ h   = (LAYER == 1) ? d_h1   : d_h2;
    const float* __restrict__ res = (LAYER == 1) ? d_res1 : d_res2;
    float* __restrict__ out       = (LAYER == 1) ? d_g1   : d_g2;

    int gw   = (blockIdx.x * blockDim.x + threadIdx.x) >> 5;
    int lane = threadIdx.x & 31;
    if (gw >= BNc) return;
    int b = gw / Nc;

    float edv = d_ed[gw];
    float lg[Kc];
    int   nb[Kc];
#pragma unroll
    for (int k = 0; k < Kc; k++) {
        nb[k] = b * Nc + d_edges[gw * Kc + k];
        float e = d_es[nb[k]] + edv;
        lg[k] = (e > 0.f) ? e : 0.2f * e;
    }
    float m = lg[0];
#pragma unroll
    for (int k = 1; k < Kc; k++) m = fmaxf(m, lg[k]);
    float sum = 0.f;
#pragma unroll
    for (int k = 0; k < Kc; k++) { lg[k] = expf(lg[k] - m); sum += lg[k]; }
    float inv = 1.0f / sum;

    for (int c = lane; c < C; c += 32) {
        float acc = 0.f;
#pragma unroll
        for (int k = 0; k < Kc; k++) acc += lg[k] * h[nb[k] * C + c];
        float v = acc * inv + bias[c] + res[gw * C + c];
        out[gw * C + c] = RELU ? fmaxf(v, 0.f) : v;
    }
}

// ---------------- 3c. GAT2 matmul (128->256), 8 nodes/block (occ 50%) ----------------
__global__ void mm2_kernel(const float* __restrict__ W,
                           const float* __restrict__ RW,
                           const float* __restrict__ as_,
                           const float* __restrict__ ad_)
{
    __shared__ float xs[8 * 128];
    __shared__ float wred[2][8][8];
    int nb0 = blockIdx.x * 8;
    int t = threadIdx.x;
    for (int i = t; i < 8 * 128; i += 256)
        xs[i] = d_g1[nb0 * 128 + i];
    __syncthreads();

    int c = t;
    float acc[8], ar[8];
#pragma unroll
    for (int r = 0; r < 8; r++) { acc[r] = 0.f; ar[r] = 0.f; }

    for (int i = 0; i < 128; i++) {
        float w  = W[i * 256 + c];
        float rw = RW[i * 256 + c];
#pragma unroll
        for (int r = 0; r < 8; r++) {
            float xv = xs[r * 128 + i];
            acc[r] += xv * w;
            ar[r]  += xv * rw;
        }
    }

    float asv = as_[c], adv = ad_[c];
    int lane = t & 31, wid = t >> 5;
#pragma unroll
    for (int r = 0; r < 8; r++) {
        d_h2[(nb0 + r) * 256 + c]   = acc[r];
        d_res2[(nb0 + r) * 256 + c] = ar[r];
        float v1 = acc[r] * asv;
        float v2 = acc[r] * adv;
#pragma unroll
        for (int o = 16; o > 0; o >>= 1) {
            v1 += __shfl_down_sync(0xffffffffu, v1, o);
            v2 += __shfl_down_sync(0xffffffffu, v2, o);
        }
        if (lane == 0) { wred[0][r][wid] = v1; wred[1][r][wid] = v2; }
    }
    __syncthreads();
    if (t < 16) {
        int r = t & 7, which = t >> 3;
        float s = 0.f;
#pragma unroll
        for (int w = 0; w < 8; w++) s += wred[which][r][w];
        if (which == 0) d_es[nb0 + r] = s;
        else            d_ed[nb0 + r] = s;
    }
}

// ---------------- 4a. NetVLAD cluster softmax (warp-shuffle reductions) --------------
__global__ void act_kernel(const float* __restrict__ cw,
                           const float* __restrict__ cb)
{
    __shared__ float xs[8 * 256];
    __shared__ float redm[8][2];
    __shared__ float reds[8][2];
    int nb0 = blockIdx.x * 8;
    int k = threadIdx.x;           // 0..63
    int lane = k & 31, wid = k >> 5;
    for (int i = k; i < 8 * 256; i += 64)
        xs[i] = d_g2[nb0 * 256 + i];
    __syncthreads();

    float acc[8];
#pragma unroll
    for (int r = 0; r < 8; r++) acc[r] = cb[k];
    for (int dd = 0; dd < 256; dd++) {
        float w = cw[dd * 64 + k];
#pragma unroll
        for (int r = 0; r < 8; r++) acc[r] += xs[r * 256 + dd] * w;
    }

    // warp-level max per r, combine 2 warps via smem
#pragma unroll
    for (int r = 0; r < 8; r++) {
        float v = acc[r];
#pragma unroll
        for (int o = 16; o > 0; o >>= 1)
            v = fmaxf(v, __shfl_xor_sync(0xffffffffu, v, o));
        if (lane == 0) redm[r][wid] = v;
    }
    __syncthreads();
    float e[8];
#pragma unroll
    for (int r = 0; r < 8; r++) {
        float m = fmaxf(redm[r][0], redm[r][1]);
        e[r] = expf(acc[r] - m);
        float s = e[r];
#pragma unroll
        for (int o = 16; o > 0; o >>= 1)
            s += __shfl_xor_sync(0xffffffffu, s, o);
        if (lane == 0) reds[r][wid] = s;
    }
    __syncthreads();
#pragma unroll
    for (int r = 0; r < 8; r++) {
        float sum = reds[r][0] + reds[r][1];
        d_act[(nb0 + r) * 64 + k] = e[r] / sum;
    }
}

// ---------------- 4b. vlad partial ----------------
__global__ void vlad_partial() {
    int b  = blockIdx.x / NCH;
    int ch = blockIdx.x % NCH;
    int t  = threadIdx.x;
    int d  = t & 255;
    int kg = t >> 8;
    int base = b * Nc + ch * CHN;

    __shared__ float sact[16 * 64];
    float acc[16];
#pragma unroll
    for (int j = 0; j < 16; j++) acc[j] = 0.f;

    int nl = t >> 6, kk = t & 63;
    for (int n0 = 0; n0 < CHN; n0 += 16) {
        sact[t] = d_act[(base + n0 + nl) * 64 + kk];
        __syncthreads();
#pragma unroll
        for (int j = 0; j < 16; j++) {
            float g = d_g2[(base + n0 + j) * 256 + d];
            const float4* arow = (const float4*)&sact[j * 64 + kg * 16];
            float4 a0 = arow[0], a1 = arow[1], a2 = arow[2], a3 = arow[3];
            acc[0]  += g * a0.x; acc[1]  += g * a0.y; acc[2]  += g * a0.z; acc[3]  += g * a0.w;
            acc[4]  += g * a1.x; acc[5]  += g * a1.y; acc[6]  += g * a1.z; acc[7]  += g * a1.w;
            acc[8]  += g * a2.x; acc[9]  += g * a2.y; acc[10] += g * a2.z; acc[11] += g * a2.w;
            acc[12] += g * a3.x; acc[13] += g * a3.y; acc[14] += g * a3.z; acc[15] += g * a3.w;
        }
        __syncthreads();
    }

    float4* dst = (float4*)&d_vpart[(((b * NCH) + ch) * 256 + d) * 64 + kg * 16];
    dst[0] = make_float4(acc[0],  acc[1],  acc[2],  acc[3]);
    dst[1] = make_float4(acc[4],  acc[5],  acc[6],  acc[7]);
    dst[2] = make_float4(acc[8],  acc[9],  acc[10], acc[11]);
    dst[3] = make_float4(acc[12], acc[13], acc[14], acc[15]);
}

// ---------------- 4c. vlad finish ----------------
__global__ void vlad_finish(const float* __restrict__ cw2) {
    int b  = blockIdx.x >> 6;
    int k  = blockIdx.x & 63;
    int dd = threadIdx.x;

    float part = 0.f;
    for (int n = dd; n < Nc; n += 256)
        part += d_act[(b * Nc + n) * 64 + k];
    __shared__ float red[256];
    red[dd] = part;
    __syncthreads();
    for (int s = 128; s > 0; s >>= 1) {
        if (dd < s) red[dd] += red[dd + s];
        __syncthreads();
    }
    float asum = red[0];
    __syncthreads();

    float v = 0.f;
#pragma unroll 5
    for (int ch = 0; ch < NCH; ch++)
        v += d_vpart[((b * NCH + ch) * 256 + dd) * 64 + k];
    v -= asum * cw2[dd * 64 + k];

    red[dd] = v * v;
    __syncthreads();
    for (int s = 128; s > 0; s >>= 1) {
        if (dd < s) red[dd] += red[dd + s];
        __syncthreads();
    }
    float ss  = red[0];
    float den = fmaxf(sqrtf(ss), 1e-12f);
    d_vlad[(b * 256 + dd) * 64 + k] = v / den;
    if (dd == 0) d_colsq[b * 64 + k] = ss / (den * den);
}

// ---------------- 4d. y partial projection ----------------
__global__ void y_partial(const float* __restrict__ h1w) {
    int b  = blockIdx.x / YCH;
    int ch = blockIdx.x % YCH;
    int o  = threadIdx.x;
    __shared__ float sv[256];
    sv[o] = d_vlad[b * 16384 + ch * 256 + o];
    __syncthreads();
    float acc = 0.f;
#pragma unroll 4
    for (int j = 0; j < 256; j++)
        acc += sv[j] * h1w[(ch * 256 + j) * 256 + o];
    d_ypart[(b * YCH + ch) * 256 + o] = acc;
}

// ---------------- 4e. reduce y + gate + output ----------------
__global__ void out_kernel(const float* __restrict__ h1b,
                           const float* __restrict__ gw,
                           const float* __restrict__ gb,
                           float* __restrict__ out)
{
    int b = blockIdx.x;
    int o = threadIdx.x;
    __shared__ float sc[64];
    __shared__ float gs;
    if (o < 64) sc[o] = d_colsq[b * 64 + o];
    __syncthreads();
    if (o == 0) {
        float s = 0.f;
        for (int i = 0; i < 64; i++) s += sc[i];
        gs = 1.0f / fmaxf(sqrtf(s), 1e-12f);
    }
    __syncthreads();

    float acc = 0.f;
#pragma unroll
    for (int ch = 0; ch < YCH; ch++)
        acc += d_ypart[(b * YCH + ch) * 256 + o];
    float y = acc * gs + h1b[o];

    __shared__ float sy[256];
    sy[o] = y;
    __syncthreads();
    float g = gb[o];
    for (int j = 0; j < 256; j++) g += sy[j] * gw[j * 256 + o];
    out[b * 256 + o] = y * (1.0f / (1.0f + expf(-g)));
}

// ---------------- launch ----------------
extern "C" void kernel_launch(void* const* d_in, const int* in_sizes, int n_in,
                              void* d_out, int out_size) {
    const float* depth    = (const float*)d_in[1];
    const float* gat1_w   = (const float*)d_in[8];
    const float* gat1_as  = (const float*)d_in[9];
    const float* gat1_ad  = (const float*)d_in[10];
    const float* gat1_b   = (const float*)d_in[11];
    const float* gat1_res = (const float*)d_in[12];
    const float* gat2_w   = (const float*)d_in[13];
    const float* gat2_as  = (const float*)d_in[14];
    const float* gat2_ad  = (const float*)d_in[15];
    const float* gat2_b   = (const float*)d_in[16];
    const float* gat2_res = (const float*)d_in[17];
    const float* vlad_cw  = (const float*)d_in[18];
    const float* vlad_cb  = (const float*)d_in[19];
    const float* vlad_cw2 = (const float*)d_in[20];
    const float* vlad_h1w = (const float*)d_in[21];
    const float* vlad_h1b = (const float*)d_in[22];
    const float* gate_w   = (const float*)d_in[23];
    const float* gate_b   = (const float*)d_in[24];
    float* out = (float*)d_out;

    ptsgat1_kernel<<<2400, 256>>>(depth, gat1_w, gat1_as, gat1_ad, gat1_res);
    nop_kernel<<<1, 32>>>(0);            // keep knn as 4th launch for ncu
    nop_kernel<<<1, 32>>>(1);
    knn_kernel<<<600, 256>>>();
    attn_kernel<1, 128, true><<<2400, 256>>>(gat1_b);
    mm2_kernel<<<2400, 256>>>(gat2_w, gat2_res, gat2_as, gat2_ad);
    attn_kernel<2, 256, false><<<2400, 256>>>(gat2_b);
    act_kernel<<<2400, 64>>>(vlad_cw, vlad_cb);
    vlad_partial<<<Bc * NCH, 1024>>>();
    vlad_finish<<<Bc * 64, 256>>>(vlad_cw2);
    y_partial<<<Bc * YCH, 256>>>(vlad_h1w);
    out_kernel<<<Bc, 256>>>(vlad_h1b, gate_w, gate_b, out);
}